// round 15
// baseline (speedup 1.0000x reference)
#include <cuda_runtime.h>
#include <cstdint>

// Problem constants
#define B_ 8
#define T_ 64
#define N_ 512
#define D_ 64
#define KH_ 8
#define NEG_ (-32767.0f)

// smem (floats), one problem per CTA:
//   H  : 64 x 132 (concat(x,ste); cols 0..63 reused as attn out O)
//   Qf : 64 x 68  (q pre-scaled by 1/sqrt(d); reused as FFN hidden U)
//   Kf : 64 x 68
//   Vf : 64 x 68
//   Ws : 64 x 72  (weight staging buffer, [k][j] with pad; conflict-free B loads)
#define H_STR   132
#define QKV_STR 68
#define WS_STR  72
#define SMEM_FLOATS (64 * H_STR + 3 * 64 * QKV_STR + 64 * WS_STR)  // 26112 floats = 104448 B

// ---- tf32 helpers: mask-based split (no cvt) ----
__device__ __forceinline__ void tf32_split(float v, uint32_t& hi, uint32_t& lo) {
    hi = __float_as_uint(v) & 0xffffe000u;
    lo = __float_as_uint(v - __uint_as_float(hi));
}
__device__ __forceinline__ void mma8(float c[4], const uint32_t a[4], const uint32_t b[2]) {
    asm volatile(
        "mma.sync.aligned.m16n8k8.row.col.f32.tf32.tf32.f32 "
        "{%0,%1,%2,%3}, {%4,%5,%6,%7}, {%8,%9}, {%0,%1,%2,%3};"
        : "+f"(c[0]), "+f"(c[1]), "+f"(c[2]), "+f"(c[3])
        : "r"(a[0]), "r"(a[1]), "r"(a[2]), "r"(a[3]), "r"(b[0]), "r"(b[1]));
}

// stage one 64x64 weight block (rows koff..koff+63 of W[k][64]) into Ws[64x72]
__device__ __forceinline__ void stage_w(float* __restrict__ Ws,
                                        const float* __restrict__ W, int tid) {
    #pragma unroll
    for (int i = 0; i < 4; i++) {
        int idx = tid + i * 256;            // 0..1023
        int r = idx >> 4, c4 = (idx & 15) << 2;
        *(float4*)&Ws[r * WS_STR + c4] = *(const float4*)&W[r * 64 + c4];
    }
}

// 32x16-tile GEMM accumulate, B staged in smem (stride 72, conflict-free):
// warp covers rows mrow*32..+32, cols ncol*16..+16. 3-term tf32 split.
template<int KSTEPS, int ASTR>
__device__ __forceinline__ void mma_gemm64(const float* __restrict__ A,
                                           const float* __restrict__ Ws,
                                           float acc[2][2][4],
                                           int mrow, int ncol, int g, int tq)
{
    const float* Ab = A + mrow * 32 * ASTR;
    #pragma unroll
    for (int kk = 0; kk < KSTEPS; kk++) {
        const int k0 = kk * 8;
        uint32_t ah[2][4], al[2][4];
        #pragma unroll
        for (int mi = 0; mi < 2; mi++) {
            const float* Am = Ab + mi * 16 * ASTR;
            tf32_split(Am[g * ASTR + k0 + tq],           ah[mi][0], al[mi][0]);
            tf32_split(Am[(g + 8) * ASTR + k0 + tq],     ah[mi][1], al[mi][1]);
            tf32_split(Am[g * ASTR + k0 + tq + 4],       ah[mi][2], al[mi][2]);
            tf32_split(Am[(g + 8) * ASTR + k0 + tq + 4], ah[mi][3], al[mi][3]);
        }
        float bv0[2], bv1[2];
        #pragma unroll
        for (int nt = 0; nt < 2; nt++) {
            const int nb = ncol * 16 + nt * 8 + g;
            bv0[nt] = Ws[(k0 + tq) * WS_STR + nb];
            bv1[nt] = Ws[(k0 + tq + 4) * WS_STR + nb];
        }
        #pragma unroll
        for (int nt = 0; nt < 2; nt++) {
            uint32_t bh[2], bl[2];
            tf32_split(bv0[nt], bh[0], bl[0]);
            tf32_split(bv1[nt], bh[1], bl[1]);
            #pragma unroll
            for (int mi = 0; mi < 2; mi++) {
                mma8(acc[mi][nt], ah[mi], bh);
                mma8(acc[mi][nt], ah[mi], bl);
                mma8(acc[mi][nt], al[mi], bh);
            }
        }
    }
}

// register softmax over one 64-wide row held as 16 values/lane across 4 tq-lanes
__device__ __forceinline__ void softmax_reg16(float* __restrict__ v) {
    float mx = v[0];
    #pragma unroll
    for (int k = 1; k < 16; k++) mx = fmaxf(mx, v[k]);
    mx = fmaxf(mx, __shfl_xor_sync(0xffffffffu, mx, 1));
    mx = fmaxf(mx, __shfl_xor_sync(0xffffffffu, mx, 2));
    float sum = 0.0f;
    #pragma unroll
    for (int k = 0; k < 16; k++) { v[k] = __expf(v[k] - mx); sum += v[k]; }
    sum += __shfl_xor_sync(0xffffffffu, sum, 1);
    sum += __shfl_xor_sync(0xffffffffu, sum, 2);
    float inv = 1.0f / sum;
    #pragma unroll
    for (int k = 0; k < 16; k++) v[k] *= inv;
}

__global__ __launch_bounds__(256, 2)
void temporal_attn_kernel(
    const float* __restrict__ x,  const float* __restrict__ ste,
    const float* __restrict__ Wq, const float* __restrict__ bq,
    const float* __restrict__ Wk, const float* __restrict__ bk,
    const float* __restrict__ Wv, const float* __restrict__ bv,
    const float* __restrict__ W1, const float* __restrict__ b1,
    const float* __restrict__ W2, const float* __restrict__ b2,
    float* __restrict__ out)
{
    extern __shared__ float sm[];
    const int tid = threadIdx.x;      // 0..255, one problem per CTA

    const int p = blockIdx.x;
    const int n = p & (N_ - 1);
    const int b = p >> 9;

    float* H  = sm;
    float* Qf = H  + 64 * H_STR;
    float* Kf = Qf + 64 * QKV_STR;
    float* Vf = Kf + 64 * QKV_STR;
    float* Ws = Vf + 64 * QKV_STR;

    // ---- load H = concat(x, ste): 64 x 128, float4 ----
    {
        const float* xb = x   + ((size_t)((size_t)b * T_) * N_ + n) * D_;
        const float* sb = ste + ((size_t)((size_t)b * T_) * N_ + n) * D_;
        #pragma unroll
        for (int i = 0; i < 4; i++) {
            int idx = tid + i * 256;
            int t = idx >> 4, f4 = (idx & 15) << 2;
            size_t g = (size_t)t * (N_ * D_) + f4;
            *(float4*)&H[t * H_STR + f4]      = *(const float4*)&xb[g];
            *(float4*)&H[t * H_STR + 64 + f4] = *(const float4*)&sb[g];
        }
    }

    // lane mapping
    const int lane  = tid & 31;
    const int wl    = tid >> 5;       // warp 0..7
    const int g     = lane >> 2;
    const int tq    = lane & 3;
    // GEMM tile mapping: 2 row-blocks x 4 col-blocks
    const int mrow  = wl & 1;
    const int ncol  = wl >> 1;
    // attention mapping (independent): 4 m-tiles x 2 head-select
    const int mtile = wl & 3;
    const int hsel  = wl >> 2;

    const float rsc = 0.3535533905932738f;   // 1/sqrt(8)

    // ---- QKV projections (3 passes): relu(H[64x128] @ W[128x64] + b) ----
    // B staged in two K-halves through Ws. Q pre-scaled by rsc at the epilogue.
    #pragma unroll 1
    for (int m = 0; m < 3; m++) {
        const float* W    = (m == 0) ? Wq : (m == 1) ? Wk : Wv;
        const float* bias = (m == 0) ? bq : (m == 1) ? bk : bv;
        float* dst        = (m == 0) ? Qf : (m == 1) ? Kf : Vf;
        const float sc    = (m == 0) ? rsc : 1.0f;

        float acc[2][2][4];
        #pragma unroll
        for (int i = 0; i < 2; i++)
            #pragma unroll
            for (int j = 0; j < 2; j++)
                #pragma unroll
                for (int c = 0; c < 4; c++) acc[i][j][c] = 0.0f;

        __syncthreads();                       // previous Ws readers done (or H load on m=0)
        stage_w(Ws, W, tid);                   // k rows 0..63
        __syncthreads();
        mma_gemm64<8, H_STR>(H, Ws, acc, mrow, ncol, g, tq);
        __syncthreads();                       // all reads of this Ws half done
        stage_w(Ws, W + 64 * 64, tid);         // k rows 64..127
        __syncthreads();
        mma_gemm64<8, H_STR>(H + 64, Ws, acc, mrow, ncol, g, tq);

        #pragma unroll
        for (int mi = 0; mi < 2; mi++) {
            #pragma unroll
            for (int nt = 0; nt < 2; nt++) {
                int j0 = ncol * 16 + nt * 8 + 2 * tq;
                float bj0 = bias[j0], bj1 = bias[j0 + 1];
                int r0 = mrow * 32 + mi * 16 + g;
                dst[r0 * QKV_STR + j0]           = fmaxf(acc[mi][nt][0] + bj0, 0.0f) * sc;
                dst[r0 * QKV_STR + j0 + 1]       = fmaxf(acc[mi][nt][1] + bj1, 0.0f) * sc;
                dst[(r0 + 8) * QKV_STR + j0]     = fmaxf(acc[mi][nt][2] + bj0, 0.0f) * sc;
                dst[(r0 + 8) * QKV_STR + j0 + 1] = fmaxf(acc[mi][nt][3] + bj1, 0.0f) * sc;
            }
        }
    }
    __syncthreads();   // Q,K,V visible; attention is barrier-free from here

    // ---- attention: fully register-resident per warp ----
    const int r0m  = mtile * 16;
    const int base4 = lane & ~3;            // g*4
    const int srcA  = base4 + (tq >> 1);    // shfl source for col k0+tq
    const int srcB  = srcA + 2;             // shfl source for col k0+tq+4

    #pragma unroll 1
    for (int hp = 0; hp < 4; hp++) {
        const int head = hp * 2 + hsel;
        const int hc   = head * 8;

        float p0[16], p1[16];   // rows ta=r0m+g and tb=ta+8, cols {n0+2tq, n0+2tq+1} per 8-group

        // scores: C-fragments, causal mask applied in registers
        {
            uint32_t ah[4], al[4];
            tf32_split(Qf[(r0m + g)     * QKV_STR + hc + tq],     ah[0], al[0]);
            tf32_split(Qf[(r0m + g + 8) * QKV_STR + hc + tq],     ah[1], al[1]);
            tf32_split(Qf[(r0m + g)     * QKV_STR + hc + tq + 4], ah[2], al[2]);
            tf32_split(Qf[(r0m + g + 8) * QKV_STR + hc + tq + 4], ah[3], al[3]);
            const int ta = r0m + g, tb = ta + 8;
            #pragma unroll
            for (int nt = 0; nt < 8; nt++) {
                const int n0 = nt * 8;
                uint32_t bh[2], bl[2];
                tf32_split(Kf[(n0 + g) * QKV_STR + hc + tq],     bh[0], bl[0]);
                tf32_split(Kf[(n0 + g) * QKV_STR + hc + tq + 4], bh[1], bl[1]);
                float c[4] = {0.f, 0.f, 0.f, 0.f};
                mma8(c, ah, bh);
                mma8(c, ah, bl);
                mma8(c, al, bh);
                const int s0 = n0 + 2 * tq;
                p0[2 * nt]     = (s0     > ta) ? NEG_ : c[0];
                p0[2 * nt + 1] = (s0 + 1 > ta) ? NEG_ : c[1];
                p1[2 * nt]     = (s0     > tb) ? NEG_ : c[2];
                p1[2 * nt + 1] = (s0 + 1 > tb) ? NEG_ : c[3];
            }
        }

        // softmax in registers
        softmax_reg16(p0);
        softmax_reg16(p1);

        // AV: shfl-transpose C-layout -> A-fragments, accumulate O
        float o[4] = {0.f, 0.f, 0.f, 0.f};
        #pragma unroll
        for (int kk = 0; kk < 8; kk++) {
            float x0 = __shfl_sync(0xffffffffu, p0[2 * kk],     srcA);
            float y0 = __shfl_sync(0xffffffffu, p0[2 * kk + 1], srcA);
            float x1 = __shfl_sync(0xffffffffu, p0[2 * kk],     srcB);
            float y1 = __shfl_sync(0xffffffffu, p0[2 * kk + 1], srcB);
            float u0 = __shfl_sync(0xffffffffu, p1[2 * kk],     srcA);
            float w0 = __shfl_sync(0xffffffffu, p1[2 * kk + 1], srcA);
            float u1 = __shfl_sync(0xffffffffu, p1[2 * kk],     srcB);
            float w1 = __shfl_sync(0xffffffffu, p1[2 * kk + 1], srcB);
            float a0f = (tq & 1) ? y0 : x0;    // P[row g][k0+tq]
            float a2f = (tq & 1) ? y1 : x1;    // P[row g][k0+tq+4]
            float a1f = (tq & 1) ? w0 : u0;    // P[row g+8][k0+tq]
            float a3f = (tq & 1) ? w1 : u1;    // P[row g+8][k0+tq+4]

            uint32_t ah[4], al[4], bh[2], bl[2];
            tf32_split(a0f, ah[0], al[0]);
            tf32_split(a1f, ah[1], al[1]);
            tf32_split(a2f, ah[2], al[2]);
            tf32_split(a3f, ah[3], al[3]);
            const int k0 = kk * 8;
            tf32_split(Vf[(k0 + tq)     * QKV_STR + hc + g], bh[0], bl[0]);
            tf32_split(Vf[(k0 + tq + 4) * QKV_STR + hc + g], bh[1], bl[1]);
            mma8(o, ah, bh);
            mma8(o, ah, bl);
            mma8(o, al, bh);
        }
        *(float2*)&H[(r0m + g)     * H_STR + hc + 2 * tq] = make_float2(o[0], o[1]);
        *(float2*)&H[(r0m + g + 8) * H_STR + hc + 2 * tq] = make_float2(o[2], o[3]);
    }
    __syncthreads();   // O complete before FFN1 (and Ws free)

    // ---- FFN layer 1: U = relu(O @ W1 + b1) -> Qf ----
    {
        float acc[2][2][4];
        #pragma unroll
        for (int i = 0; i < 2; i++)
            #pragma unroll
            for (int j = 0; j < 2; j++)
                #pragma unroll
                for (int c = 0; c < 4; c++) acc[i][j][c] = 0.0f;

        stage_w(Ws, W1, tid);
        __syncthreads();
        mma_gemm64<8, H_STR>(H, Ws, acc, mrow, ncol, g, tq);

        #pragma unroll
        for (int mi = 0; mi < 2; mi++) {
            #pragma unroll
            for (int nt = 0; nt < 2; nt++) {
                int j0 = ncol * 16 + nt * 8 + 2 * tq;
                float bj0 = b1[j0], bj1 = b1[j0 + 1];
                int r0 = mrow * 32 + mi * 16 + g;
                Qf[r0 * QKV_STR + j0]           = fmaxf(acc[mi][nt][0] + bj0, 0.0f);
                Qf[r0 * QKV_STR + j0 + 1]       = fmaxf(acc[mi][nt][1] + bj1, 0.0f);
                Qf[(r0 + 8) * QKV_STR + j0]     = fmaxf(acc[mi][nt][2] + bj0, 0.0f);
                Qf[(r0 + 8) * QKV_STR + j0 + 1] = fmaxf(acc[mi][nt][3] + bj1, 0.0f);
            }
        }
    }
    __syncthreads();   // U complete; Ws reads done

    // ---- FFN layer 2: out = U @ W2 + b2 -> global ----
    {
        float acc[2][2][4];
        #pragma unroll
        for (int i = 0; i < 2; i++)
            #pragma unroll
            for (int j = 0; j < 2; j++)
                #pragma unroll
                for (int c = 0; c < 4; c++) acc[i][j][c] = 0.0f;

        stage_w(Ws, W2, tid);
        __syncthreads();
        mma_gemm64<8, QKV_STR>(Qf, Ws, acc, mrow, ncol, g, tq);

        #pragma unroll
        for (int mi = 0; mi < 2; mi++) {
            #pragma unroll
            for (int nt = 0; nt < 2; nt++) {
                int j0 = ncol * 16 + nt * 8 + 2 * tq;
                float bj0 = b2[j0], bj1 = b2[j0 + 1];
                int r0 = mrow * 32 + mi * 16 + g;
                float* o0 = out + (((size_t)b * T_ + r0)     * N_ + n) * D_ + j0;
                float* o1 = out + (((size_t)b * T_ + r0 + 8) * N_ + n) * D_ + j0;
                o0[0] = acc[mi][nt][0] + bj0;
                o0[1] = acc[mi][nt][1] + bj1;
                o1[0] = acc[mi][nt][2] + bj0;
                o1[1] = acc[mi][nt][3] + bj1;
            }
        }
    }
}

extern "C" void kernel_launch(void* const* d_in, const int* in_sizes, int n_in,
                              void* d_out, int out_size)
{
    (void)in_sizes; (void)n_in; (void)out_size;
    const float* x   = (const float*)d_in[0];
    const float* ste = (const float*)d_in[1];
    const float* Wq  = (const float*)d_in[2];
    const float* bq  = (const float*)d_in[3];
    const float* Wk  = (const float*)d_in[4];
    const float* bk  = (const float*)d_in[5];
    const float* Wv  = (const float*)d_in[6];
    const float* bv  = (const float*)d_in[7];
    const float* W1  = (const float*)d_in[8];
    const float* b1  = (const float*)d_in[9];
    const float* W2  = (const float*)d_in[10];
    const float* b2  = (const float*)d_in[11];
    float* out = (float*)d_out;

    const int smem_bytes = SMEM_FLOATS * sizeof(float);   // 104448
    static bool attr_set = false;
    if (!attr_set) {
        cudaFuncSetAttribute(temporal_attn_kernel,
                             cudaFuncAttributeMaxDynamicSharedMemorySize,
                             smem_bytes);
        attr_set = true;
    }
    temporal_attn_kernel<<<B_ * N_, 256, smem_bytes>>>(
        x, ste, Wq, bq, Wk, bk, Wv, bv, W1, b1, W2, b2, out);
}

// round 17
// speedup vs baseline: 1.0868x; 1.0868x over previous
#include <cuda_runtime.h>
#include <cstdint>

// Problem constants
#define B_ 8
#define T_ 64
#define N_ 512
#define D_ 64
#define KH_ 8
#define NEG_ (-32767.0f)

// smem (floats), one problem per CTA (round-14 layout):
//   H  : 64 x 132 (concat(x,ste); cols 0..63 reused as attn out O)
//   Qf : 64 x 68  (q pre-scaled by 1/sqrt(d); reused as FFN hidden U)
//   Kf : 64 x 68
//   Vf : 64 x 68
#define H_STR   132
#define QKV_STR 68
#define SMEM_FLOATS (64 * H_STR + 3 * 64 * QKV_STR)   // 21504 floats = 86016 B

// Weights pre-arranged in fragment order (one float4 per lane per k-step):
// entry [(ncol*KSTEPS + kk)*32 + lane] = { W[k0+tq][nb+g], W[k0+tq+4][nb+g],
//                                          W[k0+tq][nb+8+g], W[k0+tq+4][nb+8+g] }
// with k0=kk*8, nb=ncol*16, g=lane>>2, tq=lane&3.  Bijective re-layout.
__device__ __align__(16) float4 g_wqkv[3 * 4 * 16 * 32];   // Wq,Wk,Wv (KSTEPS=16)
__device__ __align__(16) float4 g_wffn[2 * 4 * 8 * 32];    // W1,W2    (KSTEPS=8)

// ---- tf32 helpers: mask-based split (no cvt) ----
__device__ __forceinline__ void tf32_split(float v, uint32_t& hi, uint32_t& lo) {
    hi = __float_as_uint(v) & 0xffffe000u;
    lo = __float_as_uint(v - __uint_as_float(hi));
}
__device__ __forceinline__ void mma8(float c[4], const uint32_t a[4], const uint32_t b[2]) {
    asm volatile(
        "mma.sync.aligned.m16n8k8.row.col.f32.tf32.tf32.f32 "
        "{%0,%1,%2,%3}, {%4,%5,%6,%7}, {%8,%9}, {%0,%1,%2,%3};"
        : "+f"(c[0]), "+f"(c[1]), "+f"(c[2]), "+f"(c[3])
        : "r"(a[0]), "r"(a[1]), "r"(a[2]), "r"(a[3]), "r"(b[0]), "r"(b[1]));
}

// ---- prep kernel: rewrite weights into fragment order ----
__global__ void prep_weights(const float* __restrict__ Wq, const float* __restrict__ Wk,
                             const float* __restrict__ Wv, const float* __restrict__ W1,
                             const float* __restrict__ W2)
{
    int idx = blockIdx.x * 256 + threadIdx.x;     // 0..8191
    if (idx < 6144) {                             // QKV: 3 * (4*16*32 = 2048)
        int m = idx >> 11, r = idx & 2047;
        int ncol = r >> 9, r2 = r & 511;
        int kk = r2 >> 5, lane = r2 & 31;
        int g = lane >> 2, tq = lane & 3;
        int k0 = kk * 8, nb = ncol * 16 + g;
        const float* W = (m == 0) ? Wq : (m == 1) ? Wk : Wv;
        g_wqkv[idx] = make_float4(W[(k0 + tq) * 64 + nb],
                                  W[(k0 + tq + 4) * 64 + nb],
                                  W[(k0 + tq) * 64 + nb + 8],
                                  W[(k0 + tq + 4) * 64 + nb + 8]);
    } else if (idx < 8192) {                      // FFN: 2 * (4*8*32 = 1024)
        int i2 = idx - 6144;
        int m = i2 >> 10, r = i2 & 1023;
        int ncol = r >> 8, r2 = r & 255;
        int kk = r2 >> 5, lane = r2 & 31;
        int g = lane >> 2, tq = lane & 3;
        int k0 = kk * 8, nb = ncol * 16 + g;
        const float* W = (m == 0) ? W1 : W2;
        g_wffn[i2] = make_float4(W[(k0 + tq) * 64 + nb],
                                 W[(k0 + tq + 4) * 64 + nb],
                                 W[(k0 + tq) * 64 + nb + 8],
                                 W[(k0 + tq + 4) * 64 + nb + 8]);
    }
}

// 32x16-tile GEMM accumulate, B in fragment-order global (1 coalesced LDG.128/k-step):
// warp covers rows mrow*32..+32, cols ncol*16..+16. 3-term tf32 split.
template<int KSTEPS, int ASTR>
__device__ __forceinline__ void mma_gemm64(const float* __restrict__ A,
                                           const float4* __restrict__ Wp,
                                           float acc[2][2][4],
                                           int mrow, int ncol, int g, int tq)
{
    const float* Ab = A + mrow * 32 * ASTR;
    const int lane = 4 * g + tq;
    const float4* Wn = Wp + ncol * KSTEPS * 32 + lane;
    #pragma unroll
    for (int kk = 0; kk < KSTEPS; kk++) {
        const int k0 = kk * 8;
        uint32_t ah[2][4], al[2][4];
        #pragma unroll
        for (int mi = 0; mi < 2; mi++) {
            const float* Am = Ab + mi * 16 * ASTR;
            tf32_split(Am[g * ASTR + k0 + tq],           ah[mi][0], al[mi][0]);
            tf32_split(Am[(g + 8) * ASTR + k0 + tq],     ah[mi][1], al[mi][1]);
            tf32_split(Am[g * ASTR + k0 + tq + 4],       ah[mi][2], al[mi][2]);
            tf32_split(Am[(g + 8) * ASTR + k0 + tq + 4], ah[mi][3], al[mi][3]);
        }
        float4 bv = Wn[kk * 32];
        float bv0[2] = {bv.x, bv.z};    // rows k0+tq,   nt = 0,1
        float bv1[2] = {bv.y, bv.w};    // rows k0+tq+4, nt = 0,1
        #pragma unroll
        for (int nt = 0; nt < 2; nt++) {
            uint32_t bh[2], bl[2];
            tf32_split(bv0[nt], bh[0], bl[0]);
            tf32_split(bv1[nt], bh[1], bl[1]);
            #pragma unroll
            for (int mi = 0; mi < 2; mi++) {
                mma8(acc[mi][nt], ah[mi], bh);
                mma8(acc[mi][nt], ah[mi], bl);
                mma8(acc[mi][nt], al[mi], bh);
            }
        }
    }
}

// register softmax over one 64-wide row held as 16 values/lane across 4 tq-lanes
__device__ __forceinline__ void softmax_reg16(float* __restrict__ v) {
    float mx = v[0];
    #pragma unroll
    for (int k = 1; k < 16; k++) mx = fmaxf(mx, v[k]);
    mx = fmaxf(mx, __shfl_xor_sync(0xffffffffu, mx, 1));
    mx = fmaxf(mx, __shfl_xor_sync(0xffffffffu, mx, 2));
    float sum = 0.0f;
    #pragma unroll
    for (int k = 0; k < 16; k++) { v[k] = __expf(v[k] - mx); sum += v[k]; }
    sum += __shfl_xor_sync(0xffffffffu, sum, 1);
    sum += __shfl_xor_sync(0xffffffffu, sum, 2);
    float inv = 1.0f / sum;
    #pragma unroll
    for (int k = 0; k < 16; k++) v[k] *= inv;
}

__global__ __launch_bounds__(256, 2)
void temporal_attn_kernel(
    const float* __restrict__ x,  const float* __restrict__ ste,
    const float* __restrict__ bq, const float* __restrict__ bk,
    const float* __restrict__ bv, const float* __restrict__ b1,
    const float* __restrict__ b2, float* __restrict__ out)
{
    extern __shared__ float sm[];
    const int tid = threadIdx.x;      // 0..255, one problem per CTA

    const int p = blockIdx.x;
    const int n = p & (N_ - 1);
    const int b = p >> 9;

    float* H  = sm;
    float* Qf = H  + 64 * H_STR;
    float* Kf = Qf + 64 * QKV_STR;
    float* Vf = Kf + 64 * QKV_STR;

    // ---- load H = concat(x, ste): 64 x 128, float4 ----
    {
        const float* xb = x   + ((size_t)((size_t)b * T_) * N_ + n) * D_;
        const float* sb = ste + ((size_t)((size_t)b * T_) * N_ + n) * D_;
        #pragma unroll
        for (int i = 0; i < 4; i++) {
            int idx = tid + i * 256;
            int t = idx >> 4, f4 = (idx & 15) << 2;
            size_t g = (size_t)t * (N_ * D_) + f4;
            *(float4*)&H[t * H_STR + f4]      = *(const float4*)&xb[g];
            *(float4*)&H[t * H_STR + 64 + f4] = *(const float4*)&sb[g];
        }
    }
    __syncthreads();

    // lane mapping
    const int lane  = tid & 31;
    const int wl    = tid >> 5;       // warp 0..7
    const int g     = lane >> 2;
    const int tq    = lane & 3;
    // GEMM tile mapping: 2 row-blocks x 4 col-blocks
    const int mrow  = wl & 1;
    const int ncol  = wl >> 1;
    // attention mapping (independent): 4 m-tiles x 2 head-select
    const int mtile = wl & 3;
    const int hsel  = wl >> 2;

    const float rsc = 0.3535533905932738f;   // 1/sqrt(8)

    // ---- QKV projections (3 passes): relu(H[64x128] @ W[128x64] + b) ----
    // Q is pre-scaled by rsc at the epilogue.
    #pragma unroll 1
    for (int m = 0; m < 3; m++) {
        const float4* Wp  = g_wqkv + m * (4 * 16 * 32);
        const float* bias = (m == 0) ? bq : (m == 1) ? bk : bv;
        float* dst        = (m == 0) ? Qf : (m == 1) ? Kf : Vf;
        const float sc    = (m == 0) ? rsc : 1.0f;

        float acc[2][2][4];
        #pragma unroll
        for (int i = 0; i < 2; i++)
            #pragma unroll
            for (int j = 0; j < 2; j++)
                #pragma unroll
                for (int c = 0; c < 4; c++) acc[i][j][c] = 0.0f;

        mma_gemm64<16, H_STR>(H, Wp, acc, mrow, ncol, g, tq);

        #pragma unroll
        for (int mi = 0; mi < 2; mi++) {
            #pragma unroll
            for (int nt = 0; nt < 2; nt++) {
                int j0 = ncol * 16 + nt * 8 + 2 * tq;
                float bj0 = bias[j0], bj1 = bias[j0 + 1];
                int r0 = mrow * 32 + mi * 16 + g;
                dst[r0 * QKV_STR + j0]           = fmaxf(acc[mi][nt][0] + bj0, 0.0f) * sc;
                dst[r0 * QKV_STR + j0 + 1]       = fmaxf(acc[mi][nt][1] + bj1, 0.0f) * sc;
                dst[(r0 + 8) * QKV_STR + j0]     = fmaxf(acc[mi][nt][2] + bj0, 0.0f) * sc;
                dst[(r0 + 8) * QKV_STR + j0 + 1] = fmaxf(acc[mi][nt][3] + bj1, 0.0f) * sc;
            }
        }
    }
    __syncthreads();   // Q,K,V visible; attention is barrier-free from here

    // ---- attention: fully register-resident per warp ----
    const int r0m  = mtile * 16;
    const int base4 = lane & ~3;            // g*4
    const int srcA  = base4 + (tq >> 1);    // shfl source for col k0+tq
    const int srcB  = srcA + 2;             // shfl source for col k0+tq+4

    #pragma unroll 1
    for (int hp = 0; hp < 4; hp++) {
        const int head = hp * 2 + hsel;
        const int hc   = head * 8;

        float p0[16], p1[16];   // rows ta=r0m+g and tb=ta+8, cols {n0+2tq, n0+2tq+1} per 8-group

        // scores: C-fragments, causal mask applied in registers
        {
            uint32_t ah[4], al[4];
            tf32_split(Qf[(r0m + g)     * QKV_STR + hc + tq],     ah[0], al[0]);
            tf32_split(Qf[(r0m + g + 8) * QKV_STR + hc + tq],     ah[1], al[1]);
            tf32_split(Qf[(r0m + g)     * QKV_STR + hc + tq + 4], ah[2], al[2]);
            tf32_split(Qf[(r0m + g + 8) * QKV_STR + hc + tq + 4], ah[3], al[3]);
            const int ta = r0m + g, tb = ta + 8;
            #pragma unroll
            for (int nt = 0; nt < 8; nt++) {
                const int n0 = nt * 8;
                uint32_t bh[2], bl[2];
                tf32_split(Kf[(n0 + g) * QKV_STR + hc + tq],     bh[0], bl[0]);
                tf32_split(Kf[(n0 + g) * QKV_STR + hc + tq + 4], bh[1], bl[1]);
                float c[4] = {0.f, 0.f, 0.f, 0.f};
                mma8(c, ah, bh);
                mma8(c, ah, bl);
                mma8(c, al, bh);
                const int s0 = n0 + 2 * tq;
                p0[2 * nt]     = (s0     > ta) ? NEG_ : c[0];
                p0[2 * nt + 1] = (s0 + 1 > ta) ? NEG_ : c[1];
                p1[2 * nt]     = (s0     > tb) ? NEG_ : c[2];
                p1[2 * nt + 1] = (s0 + 1 > tb) ? NEG_ : c[3];
            }
        }

        // softmax in registers
        softmax_reg16(p0);
        softmax_reg16(p1);

        // AV: shfl-transpose C-layout -> A-fragments, accumulate O
        float o[4] = {0.f, 0.f, 0.f, 0.f};
        #pragma unroll
        for (int kk = 0; kk < 8; kk++) {
            float x0 = __shfl_sync(0xffffffffu, p0[2 * kk],     srcA);
            float y0 = __shfl_sync(0xffffffffu, p0[2 * kk + 1], srcA);
            float x1 = __shfl_sync(0xffffffffu, p0[2 * kk],     srcB);
            float y1 = __shfl_sync(0xffffffffu, p0[2 * kk + 1], srcB);
            float u0 = __shfl_sync(0xffffffffu, p1[2 * kk],     srcA);
            float w0 = __shfl_sync(0xffffffffu, p1[2 * kk + 1], srcA);
            float u1 = __shfl_sync(0xffffffffu, p1[2 * kk],     srcB);
            float w1 = __shfl_sync(0xffffffffu, p1[2 * kk + 1], srcB);
            float a0f = (tq & 1) ? y0 : x0;    // P[row g][k0+tq]
            float a2f = (tq & 1) ? y1 : x1;    // P[row g][k0+tq+4]
            float a1f = (tq & 1) ? w0 : u0;    // P[row g+8][k0+tq]
            float a3f = (tq & 1) ? w1 : u1;    // P[row g+8][k0+tq+4]

            uint32_t ah[4], al[4], bh[2], bl[2];
            tf32_split(a0f, ah[0], al[0]);
            tf32_split(a1f, ah[1], al[1]);
            tf32_split(a2f, ah[2], al[2]);
            tf32_split(a3f, ah[3], al[3]);
            const int k0 = kk * 8;
            tf32_split(Vf[(k0 + tq)     * QKV_STR + hc + g], bh[0], bl[0]);
            tf32_split(Vf[(k0 + tq + 4) * QKV_STR + hc + g], bh[1], bl[1]);
            mma8(o, ah, bh);
            mma8(o, ah, bl);
            mma8(o, al, bh);
        }
        *(float2*)&H[(r0m + g)     * H_STR + hc + 2 * tq] = make_float2(o[0], o[1]);
        *(float2*)&H[(r0m + g + 8) * H_STR + hc + 2 * tq] = make_float2(o[2], o[3]);
    }
    __syncthreads();   // O complete before FFN1

    // ---- FFN layer 1: U = relu(O @ W1 + b1) -> Qf ----
    {
        float acc[2][2][4];
        #pragma unroll
        for (int i = 0; i < 2; i++)
            #pragma unroll
            for (int j = 0; j < 2; j++)
                #pragma unroll
                for (int c = 0; c < 4; c++) acc[i][j][c] = 0.0f;

        mma_gemm64<8, H_STR>(H, g_wffn, acc, mrow, ncol, g, tq);

        __syncthreads();   // Qf (as q) reads done; O reads done
        #pragma unroll
        for (int mi = 0; mi < 2; mi++) {
            #pragma unroll
            for (int nt = 0; nt < 2; nt++) {
                int j0 = ncol * 16 + nt * 8 + 2 * tq;
                float bj0 = b1[j0], bj1 = b1[j0 + 1];
                int r0 = mrow * 32 + mi * 16 + g;
                Qf[r0 * QKV_STR + j0]           = fmaxf(acc[mi][nt][0] + bj0, 0.0f);
                Qf[r0 * QKV_STR + j0 + 1]       = fmaxf(acc[mi][nt][1] + bj1, 0.0f);
                Qf[(r0 + 8) * QKV_STR + j0]     = fmaxf(acc[mi][nt][2] + bj0, 0.0f);
                Qf[(r0 + 8) * QKV_STR + j0 + 1] = fmaxf(acc[mi][nt][3] + bj1, 0.0f);
            }
        }
    }
    __syncthreads();

    // ---- FFN layer 2: out = U @ W2 + b2 -> global ----
    {
        float acc[2][2][4];
        #pragma unroll
        for (int i = 0; i < 2; i++)
            #pragma unroll
            for (int j = 0; j < 2; j++)
                #pragma unroll
                for (int c = 0; c < 4; c++) acc[i][j][c] = 0.0f;

        mma_gemm64<8, QKV_STR>(Qf, g_wffn + 4 * 8 * 32, acc, mrow, ncol, g, tq);

        #pragma unroll
        for (int mi = 0; mi < 2; mi++) {
            #pragma unroll
            for (int nt = 0; nt < 2; nt++) {
                int j0 = ncol * 16 + nt * 8 + 2 * tq;
                float bj0 = b2[j0], bj1 = b2[j0 + 1];
                int r0 = mrow * 32 + mi * 16 + g;
                float* o0 = out + (((size_t)b * T_ + r0)     * N_ + n) * D_ + j0;
                float* o1 = out + (((size_t)b * T_ + r0 + 8) * N_ + n) * D_ + j0;
                o0[0] = acc[mi][nt][0] + bj0;
                o0[1] = acc[mi][nt][1] + bj1;
                o1[0] = acc[mi][nt][2] + bj0;
                o1[1] = acc[mi][nt][3] + bj1;
            }
        }
    }
}

extern "C" void kernel_launch(void* const* d_in, const int* in_sizes, int n_in,
                              void* d_out, int out_size)
{
    (void)in_sizes; (void)n_in; (void)out_size;
    const float* x   = (const float*)d_in[0];
    const float* ste = (const float*)d_in[1];
    const float* Wq  = (const float*)d_in[2];
    const float* bq  = (const float*)d_in[3];
    const float* Wk  = (const float*)d_in[4];
    const float* bk  = (const float*)d_in[5];
    const float* Wv  = (const float*)d_in[6];
    const float* bv  = (const float*)d_in[7];
    const float* W1  = (const float*)d_in[8];
    const float* b1  = (const float*)d_in[9];
    const float* W2  = (const float*)d_in[10];
    const float* b2  = (const float*)d_in[11];
    float* out = (float*)d_out;

    const int smem_bytes = SMEM_FLOATS * sizeof(float);   // 86016
    static bool attr_set = false;
    if (!attr_set) {
        cudaFuncSetAttribute(temporal_attn_kernel,
                             cudaFuncAttributeMaxDynamicSharedMemorySize,
                             smem_bytes);
        attr_set = true;
    }
    prep_weights<<<32, 256>>>(Wq, Wk, Wv, W1, W2);
    temporal_attn_kernel<<<B_ * N_, 256, smem_bytes>>>(
        x, ste, bq, bk, bv, b1, b2, out);
}